// round 16
// baseline (speedup 1.0000x reference)
#include <cuda_runtime.h>
#include <cuda_bf16.h>
#include <cuda_pipeline.h>

// SRU PROJ forward:
//   g1  = sigmoid(u1 + bias)
//   cur = (cur - u0) * g1 + u0
// u: [L, B, D, 2] f32, bias: [D], init: [B, D]
// out: c: [L, B, D] (+ last: [B, D] appended).
//
// R15: revert to R11's 128-block aligned layout (R13's 148-block balanced
// chunks broke 128B alignment -> extra sectors, DRAM 78.9->75.6%), and
// refine FIFO granularity: GSTEPS=2 / NGRP=16 (same 32 staged timesteps,
// 64KB). Finer commit groups release waits after 2 loads instead of 4,
// shrinking per-wait SMSP idle (1 warp/SMSP -> waits are hard stalls) and
// holding the in-flight window at 30-32 steps instead of 28-32.

#define TPB    128
#define GSTEPS 2                     // timesteps per commit group
#define NGRP   16                    // rolling groups
#define STEPS  (GSTEPS * NGRP)       // 32 staged timesteps

__global__ __launch_bounds__(TPB, 1)
void sru_fwd_kernel(const float4* __restrict__ u4,   // 2 cols per float4
                    const float*  __restrict__ bias,
                    const float2* __restrict__ init2,
                    float2*       __restrict__ c2,
                    float2*       __restrict__ last2,
                    int L, int BD2, int D2)
{
    __shared__ float4 stage[STEPS][TPB];   // 64 KB

    const int tid = threadIdx.x;
    const int idx = blockIdx.x * TPB + tid;   // column-pair index (128B-aligned chunks)
    if (idx >= BD2) return;

    const int dpair = idx % D2;
    const float b0 = __ldg(&bias[2 * dpair]);
    const float b1 = __ldg(&bias[2 * dpair + 1]);

    const float2 ini = init2[idx];
    float cur0 = ini.x, cur1 = ini.y;

    const float4* up = u4 + idx;   // stride BD2 float4 per timestep
    float2*       cp = c2 + idx;   // stride BD2 float2 per timestep

    const int ngroups = L / GSTEPS;          // 512 for L=1024

    // Prologue: issue NGRP groups.
    #pragma unroll
    for (int g = 0; g < NGRP; ++g) {
        #pragma unroll
        for (int s = 0; s < GSTEPS; ++s) {
            const int l = g * GSTEPS + s;
            if (l < L)
                __pipeline_memcpy_async(&stage[g * GSTEPS + s][tid],
                                        &up[(size_t)l * BD2], sizeof(float4));
        }
        __pipeline_commit();
    }

    // Main loop: outer strides of NGRP keep slot indices compile-time.
    for (int ob = 0; ob < ngroups; ob += NGRP) {
        #pragma unroll
        for (int g = 0; g < NGRP; ++g) {
            const int grp = ob + g;

            // Wait for the oldest group (this one); NGRP-1 newer in flight.
            __pipeline_wait_prior(NGRP - 1);

            // Read the staged timesteps into registers first.
            float4 v[GSTEPS];
            #pragma unroll
            for (int s = 0; s < GSTEPS; ++s)
                v[s] = stage[g * GSTEPS + s][tid];

            // Refill this group's slots with timesteps NGRP groups ahead.
            const int nt = grp + NGRP;
            if (nt < ngroups) {
                #pragma unroll
                for (int s = 0; s < GSTEPS; ++s)
                    __pipeline_memcpy_async(&stage[g * GSTEPS + s][tid],
                                            &up[(size_t)(nt * GSTEPS + s) * BD2],
                                            sizeof(float4));
            }
            __pipeline_commit();   // always, to keep group accounting uniform

            // Compute + stream the timesteps.
            const int lbase = grp * GSTEPS;
            #pragma unroll
            for (int s = 0; s < GSTEPS; ++s) {
                const float4 w = v[s];
                const float g0 = __fdividef(1.0f, 1.0f + __expf(-(w.y + b0)));
                const float g1 = __fdividef(1.0f, 1.0f + __expf(-(w.w + b1)));
                cur0 = fmaf(cur0 - w.x, g0, w.x);
                cur1 = fmaf(cur1 - w.z, g1, w.z);
                __stcs(&cp[(size_t)(lbase + s) * BD2], make_float2(cur0, cur1));
            }
        }
    }

    // Generic tail if L not divisible by GSTEPS (not hit for L=1024).
    for (int l = ngroups * GSTEPS; l < L; ++l) {
        const float4 w = __ldcs(&up[(size_t)l * BD2]);
        const float g0 = __fdividef(1.0f, 1.0f + __expf(-(w.y + b0)));
        const float g1 = __fdividef(1.0f, 1.0f + __expf(-(w.w + b1)));
        cur0 = fmaf(cur0 - w.x, g0, w.x);
        cur1 = fmaf(cur1 - w.z, g1, w.z);
        __stcs(&cp[(size_t)l * BD2], make_float2(cur0, cur1));
    }

    if (last2) last2[idx] = make_float2(cur0, cur1);
}

extern "C" void kernel_launch(void* const* d_in, const int* in_sizes, int n_in,
                              void* d_out, int out_size)
{
    const float4* u4    = (const float4*)d_in[0];
    const float*  bias  = (const float*) d_in[1];
    const float2* init2 = (const float2*)d_in[2];

    const int D   = in_sizes[1];            // 1024
    const int BD  = in_sizes[2];            // B * D = 32768
    const int L   = in_sizes[0] / (BD * 2); // 1024
    const int BD2 = BD / 2;                 // 16384
    const int D2  = D / 2;

    float2* c2 = (float2*)d_out;
    float2* last2 = nullptr;
    const long long c_elems = (long long)L * (long long)BD;
    if ((long long)out_size >= c_elems + BD) {
        last2 = (float2*)((float*)d_out + c_elems);
    }

    const int blocks = (BD2 + TPB - 1) / TPB;   // 128
    sru_fwd_kernel<<<blocks, TPB>>>(u4, bias, init2, c2, last2, L, BD2, D2);
}

// round 17
// speedup vs baseline: 1.1677x; 1.1677x over previous
#include <cuda_runtime.h>
#include <cuda_bf16.h>
#include <cuda_pipeline.h>

// SRU PROJ forward:
//   g1  = sigmoid(u1 + bias)
//   cur = (cur - u0) * g1 + u0
// u: [L, B, D, 2] f32, bias: [D], init: [B, D]
// out: c: [L, B, D] (+ last: [B, D] appended).
//
// R16: R11's exact structure (the proven local optimum: GSTEPS=4 commit
// cadence, 128 aligned blocks x 128 threads, cp.async.cg 16B FIFO pipeline)
// with the rolling window doubled: NGRP=16 -> 64 staged timesteps, 128KB
// smem (fits the 228KB carveout, still 1 block/SM). Same commit bookkeeping
// per byte as R11; the extra window absorbs per-group DRAM service jitter
// that hard-stalls the single warp per SMSP.

#define TPB    128
#define GSTEPS 4                     // timesteps per commit group (R11 cadence)
#define NGRP   16                    // rolling groups (R11 had 8)
#define STEPS  (GSTEPS * NGRP)       // 64 staged timesteps

__global__ __launch_bounds__(TPB, 1)
void sru_fwd_kernel(const float4* __restrict__ u4,   // 2 cols per float4
                    const float*  __restrict__ bias,
                    const float2* __restrict__ init2,
                    float2*       __restrict__ c2,
                    float2*       __restrict__ last2,
                    int L, int BD2, int D2)
{
    extern __shared__ float4 stage[];   // [STEPS][TPB] = 128 KB

    const int tid = threadIdx.x;
    const int idx = blockIdx.x * TPB + tid;   // column-pair index (128B-aligned)
    if (idx >= BD2) return;

    const int dpair = idx % D2;
    const float b0 = __ldg(&bias[2 * dpair]);
    const float b1 = __ldg(&bias[2 * dpair + 1]);

    const float2 ini = init2[idx];
    float cur0 = ini.x, cur1 = ini.y;

    const float4* up = u4 + idx;   // stride BD2 float4 per timestep
    float2*       cp = c2 + idx;   // stride BD2 float2 per timestep

    const int ngroups = L / GSTEPS;          // 256 for L=1024 (divisible by NGRP)

    // Prologue: issue NGRP groups.
    #pragma unroll
    for (int g = 0; g < NGRP; ++g) {
        #pragma unroll
        for (int s = 0; s < GSTEPS; ++s) {
            const int l = g * GSTEPS + s;
            if (l < L)
                __pipeline_memcpy_async(&stage[(g * GSTEPS + s) * TPB + tid],
                                        &up[(size_t)l * BD2], sizeof(float4));
        }
        __pipeline_commit();
    }

    // Main loop: outer strides of NGRP keep slot indices compile-time.
    for (int ob = 0; ob < ngroups; ob += NGRP) {
        #pragma unroll
        for (int g = 0; g < NGRP; ++g) {
            const int grp = ob + g;

            // Wait for the oldest group (this one); NGRP-1 newer in flight.
            __pipeline_wait_prior(NGRP - 1);

            // Read the staged timesteps into registers first.
            float4 v[GSTEPS];
            #pragma unroll
            for (int s = 0; s < GSTEPS; ++s)
                v[s] = stage[(g * GSTEPS + s) * TPB + tid];

            // Refill this group's slots with timesteps NGRP groups ahead.
            const int nt = grp + NGRP;
            if (nt < ngroups) {
                #pragma unroll
                for (int s = 0; s < GSTEPS; ++s)
                    __pipeline_memcpy_async(&stage[(g * GSTEPS + s) * TPB + tid],
                                            &up[(size_t)(nt * GSTEPS + s) * BD2],
                                            sizeof(float4));
            }
            __pipeline_commit();   // always, to keep group accounting uniform

            // Compute + stream the timesteps.
            const int lbase = grp * GSTEPS;
            #pragma unroll
            for (int s = 0; s < GSTEPS; ++s) {
                const float4 w = v[s];
                const float g0 = __fdividef(1.0f, 1.0f + __expf(-(w.y + b0)));
                const float g1 = __fdividef(1.0f, 1.0f + __expf(-(w.w + b1)));
                cur0 = fmaf(cur0 - w.x, g0, w.x);
                cur1 = fmaf(cur1 - w.z, g1, w.z);
                __stcs(&cp[(size_t)(lbase + s) * BD2], make_float2(cur0, cur1));
            }
        }
    }

    // Generic tail if L not divisible by GSTEPS (not hit for L=1024).
    for (int l = ngroups * GSTEPS; l < L; ++l) {
        const float4 w = __ldcs(&up[(size_t)l * BD2]);
        const float g0 = __fdividef(1.0f, 1.0f + __expf(-(w.y + b0)));
        const float g1 = __fdividef(1.0f, 1.0f + __expf(-(w.w + b1)));
        cur0 = fmaf(cur0 - w.x, g0, w.x);
        cur1 = fmaf(cur1 - w.z, g1, w.z);
        __stcs(&cp[(size_t)l * BD2], make_float2(cur0, cur1));
    }

    if (last2) last2[idx] = make_float2(cur0, cur1);
}

extern "C" void kernel_launch(void* const* d_in, const int* in_sizes, int n_in,
                              void* d_out, int out_size)
{
    const float4* u4    = (const float4*)d_in[0];
    const float*  bias  = (const float*) d_in[1];
    const float2* init2 = (const float2*)d_in[2];

    const int D   = in_sizes[1];            // 1024
    const int BD  = in_sizes[2];            // B * D = 32768
    const int L   = in_sizes[0] / (BD * 2); // 1024
    const int BD2 = BD / 2;                 // 16384
    const int D2  = D / 2;

    float2* c2 = (float2*)d_out;
    float2* last2 = nullptr;
    const long long c_elems = (long long)L * (long long)BD;
    if ((long long)out_size >= c_elems + BD) {
        last2 = (float2*)((float*)d_out + c_elems);
    }

    const int smem_bytes = STEPS * TPB * (int)sizeof(float4);   // 128 KB
    cudaFuncSetAttribute(sru_fwd_kernel,
                         cudaFuncAttributeMaxDynamicSharedMemorySize, smem_bytes);

    const int blocks = (BD2 + TPB - 1) / TPB;   // 128
    sru_fwd_kernel<<<blocks, TPB, smem_bytes>>>(u4, bias, init2, c2, last2, L, BD2, D2);
}